// round 1
// baseline (speedup 1.0000x reference)
#include <cuda_runtime.h>
#include <cuda_bf16.h>
#include <math.h>

// loss_soft_add: per row of 25 floats, 6 chunks of 4 -> 3*softmax(chunk),
// L1 diff vs tar over first 24 cols, mean over 24, summed over all rows.
// Output: single float scalar.

#define ROWS_PER_TILE 256
#define ROW_LEN       25
#define FLOATS_PER_TILE (ROWS_PER_TILE * ROW_LEN)   // 6400
#define VEC4_PER_TILE   (FLOATS_PER_TILE / 4)       // 1600

__device__ double g_acc;

__global__ void init_kernel() {
    g_acc = 0.0;
}

__global__ __launch_bounds__(ROWS_PER_TILE)
void loss_kernel(const float* __restrict__ pre,
                 const float* __restrict__ tar,
                 long long nrows)
{
    __shared__ float sbuf[FLOATS_PER_TILE];
    __shared__ float red[ROWS_PER_TILE];

    const int tid = threadIdx.x;
    const long long ntiles = nrows / ROWS_PER_TILE;

    float acc = 0.0f;

    for (long long tile = blockIdx.x; tile < ntiles; tile += gridDim.x) {
        const long long base = tile * (long long)FLOATS_PER_TILE;

        // ---- stage PRE tile (coalesced float4) ----
        {
            const float4* p4 = reinterpret_cast<const float4*>(pre + base);
            float4* s4 = reinterpret_cast<float4*>(sbuf);
            #pragma unroll
            for (int i = tid; i < VEC4_PER_TILE; i += ROWS_PER_TILE)
                s4[i] = p4[i];
        }
        __syncthreads();

        // ---- compute 3*softmax per 4-chunk; keep out24 in registers ----
        float o[24];
        {
            const float* row = sbuf + tid * ROW_LEN;  // stride 25: bank-conflict-free
            #pragma unroll
            for (int j = 0; j < 6; j++) {
                float a = row[4 * j + 0];
                float b = row[4 * j + 1];
                float c = row[4 * j + 2];
                float d = row[4 * j + 3];
                float m = fmaxf(fmaxf(a, b), fmaxf(c, d));
                float ea = __expf(a - m);
                float eb = __expf(b - m);
                float ec = __expf(c - m);
                float ed = __expf(d - m);
                float inv = 3.0f / (ea + eb + ec + ed);
                o[4 * j + 0] = ea * inv;
                o[4 * j + 1] = eb * inv;
                o[4 * j + 2] = ec * inv;
                o[4 * j + 3] = ed * inv;
            }
        }
        __syncthreads();

        // ---- stage TAR tile into the same buffer ----
        {
            const float4* t4 = reinterpret_cast<const float4*>(tar + base);
            float4* s4 = reinterpret_cast<float4*>(sbuf);
            #pragma unroll
            for (int i = tid; i < VEC4_PER_TILE; i += ROWS_PER_TILE)
                s4[i] = t4[i];
        }
        __syncthreads();

        // ---- L1 diff over 24 elems ----
        {
            const float* row = sbuf + tid * ROW_LEN;
            float s = 0.0f;
            #pragma unroll
            for (int k = 0; k < 24; k++)
                s += fabsf(o[k] - row[k]);
            acc += s;
        }
        __syncthreads();  // before next tile overwrites sbuf
    }

    // ---- tail rows (nrows not multiple of 256), handled by block 0 ----
    {
        const long long done = ntiles * (long long)ROWS_PER_TILE;
        const long long rem = nrows - done;
        if (blockIdx.x == 0 && (long long)tid < rem) {
            const float* prow = pre + (done + tid) * (long long)ROW_LEN;
            const float* trow = tar + (done + tid) * (long long)ROW_LEN;
            float s = 0.0f;
            #pragma unroll
            for (int j = 0; j < 6; j++) {
                float a = prow[4 * j + 0];
                float b = prow[4 * j + 1];
                float c = prow[4 * j + 2];
                float d = prow[4 * j + 3];
                float m = fmaxf(fmaxf(a, b), fmaxf(c, d));
                float ea = __expf(a - m);
                float eb = __expf(b - m);
                float ec = __expf(c - m);
                float ed = __expf(d - m);
                float inv = 3.0f / (ea + eb + ec + ed);
                s += fabsf(ea * inv - trow[4 * j + 0]);
                s += fabsf(eb * inv - trow[4 * j + 1]);
                s += fabsf(ec * inv - trow[4 * j + 2]);
                s += fabsf(ed * inv - trow[4 * j + 3]);
            }
            acc += s;
        }
    }

    // ---- block reduction, one double atomic per block ----
    red[tid] = acc;
    __syncthreads();
    #pragma unroll
    for (int s = ROWS_PER_TILE / 2; s > 0; s >>= 1) {
        if (tid < s) red[tid] += red[tid + s];
        __syncthreads();
    }
    if (tid == 0)
        atomicAdd(&g_acc, (double)red[0]);
}

__global__ void finalize_kernel(float* out) {
    out[0] = (float)(g_acc * (1.0 / 24.0));
}

extern "C" void kernel_launch(void* const* d_in, const int* in_sizes, int n_in,
                              void* d_out, int out_size)
{
    const float* pre = (const float*)d_in[0];
    const float* tar = (const float*)d_in[1];
    long long nrows = (long long)in_sizes[0] / ROW_LEN;

    long long ntiles = nrows / ROWS_PER_TILE;
    int grid = (int)((ntiles < 1184) ? (ntiles > 0 ? ntiles : 1) : 1184);

    init_kernel<<<1, 1>>>();
    loss_kernel<<<grid, ROWS_PER_TILE>>>(pre, tar, nrows);
    finalize_kernel<<<1, 1>>>((float*)d_out);
}